// round 5
// baseline (speedup 1.0000x reference)
#include <cuda_runtime.h>
#include <cstdint>

// RecurrentCharLM: B=256, S=32, H=128, VOCAB=256, DEPTH=100, L=1.
// Rows of h are fully independent -> 128 persistent blocks x 2 rows, no
// inter-block comm. W column j lives in thread j's registers (128 regs),
// packed along k for fma.rn.f32x2 (Blackwell packed-fp32 2x path).

#define BATCH 256
#define SEQ   32
#define HID   128
#define VOC   256
#define DEPTH_IT 100
#define NBLK  128
#define NTHR  128

typedef unsigned long long ull;

__device__ __forceinline__ ull pack2(float lo, float hi) {
    ull r; asm("mov.b64 %0, {%1,%2};" : "=l"(r) : "f"(lo), "f"(hi)); return r;
}
__device__ __forceinline__ void unpack2(ull v, float &lo, float &hi) {
    asm("mov.b64 {%0,%1}, %2;" : "=f"(lo), "=f"(hi) : "l"(v));
}
__device__ __forceinline__ ull fma2(ull a, ull b, ull c) {
    ull d; asm("fma.rn.f32x2 %0, %1, %2, %3;" : "=l"(d) : "l"(a), "l"(b), "l"(c));
    return d;
}
__device__ __forceinline__ ull add2(ull a, ull b) {
    ull d; asm("add.rn.f32x2 %0, %1, %2;" : "=l"(d) : "l"(a), "l"(b)); return d;
}
__device__ __forceinline__ ull d2u(double x) { return __double_as_longlong(x); }

__global__ void __launch_bounds__(NTHR, 1)
rnn_charlm_kernel(const int* __restrict__ chars,
                  const float* __restrict__ hidden,
                  const float* __restrict__ embed_w,
                  const float* __restrict__ Wg,      // (1,128,128): W[k][j]
                  const float* __restrict__ ro_w,    // (256,128)
                  const float* __restrict__ ro_b,    // (256,)
                  float* __restrict__ out, int out_size)
{
    // dynamic smem: ro_w in k-paired transposed layout
    // ro_p[(k>>1)*512 + 2*v + (k&1)] = ro_w[v][k]   (64*512 floats = 128KB)
    extern __shared__ float ro_p[];
    __shared__ __align__(16) float hs[2][2][HID];   // [buf][row][k]

    const int j  = threadIdx.x;
    const int r0 = blockIdx.x * 2;
    const int r1 = r0 + 1;

    // ---- W column j into registers, packed along k: wq[m] = (W[2m][j], W[2m+1][j])
    ull wq[64];
#pragma unroll
    for (int m = 0; m < 64; ++m)
        wq[m] = pack2(Wg[(2 * m) * HID + j], Wg[(2 * m + 1) * HID + j]);

    // ---- stage ro_w into smem (coalesced global read, scattered smem write; once)
    for (int idx = j; idx < VOC * HID; idx += NTHR) {
        int v = idx / HID, k = idx % HID;
        ro_p[(k >> 1) * 512 + 2 * v + (k & 1)] = ro_w[idx];
    }

    float h0  = hidden[r0 * HID + j];
    float h1  = hidden[r1 * HID + j];
    const float rb_lo = ro_b[j];
    const float rb_hi = ro_b[j + 128];
    __syncthreads();

    for (int t = 0; t < SEQ; ++t) {
        // embed add (h = h + emb_t)
        const int c0 = chars[r0 * SEQ + t];
        const int c1 = chars[r1 * SEQ + t];
        h0 += embed_w[c0 * HID + j];
        h1 += embed_w[c1 * HID + j];

        int cur = 0;
        hs[0][0][j] = h0;
        hs[0][1][j] = h1;
        __syncthreads();

        // ---- 100 chained relu(h @ W) iterations
        for (int it = 0; it < DEPTH_IT; ++it) {
            const double2* p0 = (const double2*)hs[cur][0];
            const double2* p1 = (const double2*)hs[cur][1];
            ull a0e = 0, a0o = 0, a1e = 0, a1o = 0;
#pragma unroll
            for (int q = 0; q < 32; ++q) {          // 4 k per q
                double2 x0 = p0[q];                 // (h0[4q],h0[4q+1]) | (h0[4q+2],h0[4q+3])
                double2 x1 = p1[q];
                a0e = fma2(d2u(x0.x), wq[2 * q],     a0e);
                a0o = fma2(d2u(x0.y), wq[2 * q + 1], a0o);
                a1e = fma2(d2u(x1.x), wq[2 * q],     a1e);
                a1o = fma2(d2u(x1.y), wq[2 * q + 1], a1o);
            }
            ull s0 = add2(a0e, a0o);
            ull s1 = add2(a1e, a1o);
            float lo, hi;
            unpack2(s0, lo, hi); h0 = fmaxf(lo + hi, 0.0f);
            unpack2(s1, lo, hi); h1 = fmaxf(lo + hi, 0.0f);
            cur ^= 1;
            hs[cur][0][j] = h0;
            hs[cur][1][j] = h1;
            __syncthreads();
        }

        // ---- readout: logits[r][v] for v = j and v = j+128
        {
            const double2* p0 = (const double2*)hs[cur][0];
            const double2* p1 = (const double2*)hs[cur][1];
            ull A00 = 0, A01 = 0, A10 = 0, A11 = 0;   // [row][v-slot]
#pragma unroll
            for (int q = 0; q < 32; ++q) {            // 2 k-pairs per q
                double2 x0 = p0[q];
                double2 x1 = p1[q];
                const float* b0 = &ro_p[(2 * q) * 512];
                const float* b1 = &ro_p[(2 * q + 1) * 512];
                ull ra0 = *(const ull*)&b0[2 * j];
                ull rc0 = *(const ull*)&b0[256 + 2 * j];
                ull ra1 = *(const ull*)&b1[2 * j];
                ull rc1 = *(const ull*)&b1[256 + 2 * j];
                A00 = fma2(d2u(x0.x), ra0, A00);
                A01 = fma2(d2u(x0.x), rc0, A01);
                A10 = fma2(d2u(x1.x), ra0, A10);
                A11 = fma2(d2u(x1.x), rc0, A11);
                A00 = fma2(d2u(x0.y), ra1, A00);
                A01 = fma2(d2u(x0.y), rc1, A01);
                A10 = fma2(d2u(x1.y), ra1, A10);
                A11 = fma2(d2u(x1.y), rc1, A11);
            }
            float lo, hi;
            float* o0 = out + (r0 * SEQ + t) * VOC;
            float* o1 = out + (r1 * SEQ + t) * VOC;
            unpack2(A00, lo, hi); o0[j]       = lo + hi + rb_lo;
            unpack2(A01, lo, hi); o0[j + 128] = lo + hi + rb_hi;
            unpack2(A10, lo, hi); o1[j]       = lo + hi + rb_lo;
            unpack2(A11, lo, hi); o1[j + 128] = lo + hi + rb_hi;
        }
        // protect hs[0] (written at next timestep start) from readers still in readout
        __syncthreads();
    }

    // ---- h_final (if the harness output includes it after the logits)
    if (out_size >= BATCH * SEQ * VOC + BATCH * HID) {
        float* hf = out + BATCH * SEQ * VOC;
        hf[r0 * HID + j] = h0;
        hf[r1 * HID + j] = h1;
    }
}

extern "C" void kernel_launch(void* const* d_in, const int* in_sizes, int n_in,
                              void* d_out, int out_size)
{
    (void)in_sizes; (void)n_in;
    const int*   chars   = (const int*)d_in[0];
    const float* hidden  = (const float*)d_in[1];
    const float* embed_w = (const float*)d_in[2];
    const float* Ws      = (const float*)d_in[3];
    const float* ro_w    = (const float*)d_in[4];
    const float* ro_b    = (const float*)d_in[5];
    float* out = (float*)d_out;

    const size_t smem = 64 * 512 * sizeof(float);   // 128KB dynamic
    cudaFuncSetAttribute(rnn_charlm_kernel,
                         cudaFuncAttributeMaxDynamicSharedMemorySize, (int)smem);
    rnn_charlm_kernel<<<NBLK, NTHR, smem>>>(chars, hidden, embed_w, Ws,
                                            ro_w, ro_b, out, out_size);
}